// round 15
// baseline (speedup 1.0000x reference)
#include <cuda_runtime.h>
#include <math.h>

// MaskedNorm: B=8, T=4096, C=1024 fp32. Two launches:
// k1: dense read; masked rows -> partial sums, unmasked rows -> copy to out
//     (also resets the stats-done flag)
// k3: blocks 0-31 fold partials -> scale/shift, flag; all 1216 blocks then
//     normalize masked rows (consumers prefetch first quad before spinning).

#define CCH   1024
#define C4    (CCH / 4)      // 256 float4 per row
#define RTOT  32768          // B*T
#define R4TOT (RTOT / 4)     // 8192 row-quads
#define NBLK  296            // k1 blocks: 2/SM x 148 SMs (1024 thr each)
#define NB3   1216           // finish blocks (all normalize; 0..31 also stats)
#define EPSF  1e-4f

__device__ __align__(16) float g_psum[NBLK][CCH];
__device__ __align__(16) float g_psq [NBLK][CCH];
__device__ int   g_pcnt[NBLK];
__device__ __align__(16) float g_scale[CCH];
__device__ __align__(16) float g_shift[CCH];
__device__ int   g_sdone;        // stats-done counter (reset by k1)

__device__ __forceinline__ void acc4(float4& s, float4& q, const float4 v) {
    s.x += v.x; s.y += v.y; s.z += v.z; s.w += v.w;
    q.x = fmaf(v.x, v.x, q.x);
    q.y = fmaf(v.y, v.y, q.y);
    q.z = fmaf(v.z, v.z, q.z);
    q.w = fmaf(v.w, v.w, q.w);
}

// ---------- k1: masked reduce + unmasked copy (dense streaming) ----------
__global__ __launch_bounds__(1024, 2)
void mn_main(const float4* __restrict__ y4, const int4* __restrict__ mask4,
             float4* __restrict__ out4) {
    if (blockIdx.x == 0 && threadIdx.x == 0) g_sdone = 0;  // reset for mn_finish

    __shared__ float4 ssum[4][256];
    __shared__ float4 ssq [4][256];
    __shared__ int    scnt[4];
    const int t = threadIdx.x & 255;   // channel slot (4 channels)
    const int g = threadIdx.x >> 8;    // row group 0..3
    const int p = blockIdx.x;

    float4 s = make_float4(0.f, 0.f, 0.f, 0.f);
    float4 q = make_float4(0.f, 0.f, 0.f, 0.f);
    int cnt = 0;

    for (int r4 = p * 4 + g; r4 < R4TOT; r4 += NBLK * 4) {
        const int  r  = r4 * 4;
        const int4 mk = __ldg(&mask4[r4]);
        if (mk.x > 0) { acc4(s, q, __ldg(&y4[(r + 0) * C4 + t])); cnt++; }
        else          { __stcs(&out4[(r + 0) * C4 + t], __ldcs(&y4[(r + 0) * C4 + t])); }
        if (mk.y > 0) { acc4(s, q, __ldg(&y4[(r + 1) * C4 + t])); cnt++; }
        else          { __stcs(&out4[(r + 1) * C4 + t], __ldcs(&y4[(r + 1) * C4 + t])); }
        if (mk.z > 0) { acc4(s, q, __ldg(&y4[(r + 2) * C4 + t])); cnt++; }
        else          { __stcs(&out4[(r + 2) * C4 + t], __ldcs(&y4[(r + 2) * C4 + t])); }
        if (mk.w > 0) { acc4(s, q, __ldg(&y4[(r + 3) * C4 + t])); cnt++; }
        else          { __stcs(&out4[(r + 3) * C4 + t], __ldcs(&y4[(r + 3) * C4 + t])); }
    }
    ssum[g][t] = s;
    ssq [g][t] = q;
    if (t == 0) scnt[g] = cnt;   // identical across t within a group
    __syncthreads();

    if (g == 0) {
        float4 S = ssum[0][t], Q = ssq[0][t];
        #pragma unroll
        for (int i = 1; i < 4; i++) {
            const float4 a = ssum[i][t], b = ssq[i][t];
            S.x += a.x; S.y += a.y; S.z += a.z; S.w += a.w;
            Q.x += b.x; Q.y += b.y; Q.z += b.z; Q.w += b.w;
        }
        reinterpret_cast<float4*>(g_psum[p])[t] = S;
        reinterpret_cast<float4*>(g_psq [p])[t] = Q;
        if (t == 0) g_pcnt[p] = scnt[0] + scnt[1] + scnt[2] + scnt[3];
    }
}

// ---------- normalize one row-quad (channel slot t, guarded per row) ----------
__device__ __forceinline__ void norm_quad(const float4* __restrict__ y4,
                                          const int4 mk, float4* __restrict__ out4,
                                          const float4 sc, const float4 sh,
                                          const int r4, const int t) {
    const int r = r4 * 4;
    if (mk.x > 0) {
        float4 v = __ldg(&y4[(r + 0) * C4 + t]);
        v.x = fmaf(v.x, sc.x, sh.x); v.y = fmaf(v.y, sc.y, sh.y);
        v.z = fmaf(v.z, sc.z, sh.z); v.w = fmaf(v.w, sc.w, sh.w);
        __stcs(&out4[(r + 0) * C4 + t], v);
    }
    if (mk.y > 0) {
        float4 v = __ldg(&y4[(r + 1) * C4 + t]);
        v.x = fmaf(v.x, sc.x, sh.x); v.y = fmaf(v.y, sc.y, sh.y);
        v.z = fmaf(v.z, sc.z, sh.z); v.w = fmaf(v.w, sc.w, sh.w);
        __stcs(&out4[(r + 1) * C4 + t], v);
    }
    if (mk.z > 0) {
        float4 v = __ldg(&y4[(r + 2) * C4 + t]);
        v.x = fmaf(v.x, sc.x, sh.x); v.y = fmaf(v.y, sc.y, sh.y);
        v.z = fmaf(v.z, sc.z, sh.z); v.w = fmaf(v.w, sc.w, sh.w);
        __stcs(&out4[(r + 2) * C4 + t], v);
    }
    if (mk.w > 0) {
        float4 v = __ldg(&y4[(r + 3) * C4 + t]);
        v.x = fmaf(v.x, sc.x, sh.x); v.y = fmaf(v.y, sc.y, sh.y);
        v.z = fmaf(v.z, sc.z, sh.z); v.w = fmaf(v.w, sc.w, sh.w);
        __stcs(&out4[(r + 3) * C4 + t], v);
    }
}

// ---------- k3: in-kernel stats (blocks 0-31) + normalize (all blocks) ----------
__global__ __launch_bounds__(1024, 2)
void mn_finish(const float4* __restrict__ y4, const int4* __restrict__ mask4,
               const float* __restrict__ gamma, const float* __restrict__ beta,
               float4* __restrict__ out4) {
    __shared__ float sfs[32][33];
    __shared__ float sfq[32][33];
    __shared__ int   sn;
    const int tid  = threadIdx.x;
    const int lane = tid & 31;
    const int w    = tid >> 5;
    const int t    = tid & 255;    // channel slot for normalize
    const int g    = tid >> 8;     // row group 0..3
    const int bid  = blockIdx.x;

    // Prefetch first row-quad (consumers) BEFORE waiting on stats.
    const int r4_0 = bid * 4 + g;
    int4   mk0 = make_int4(0, 0, 0, 0);
    float4 p0, p1, p2, p3;
    if (bid >= 32 && r4_0 < R4TOT) {
        mk0 = __ldg(&mask4[r4_0]);
        const int r = r4_0 * 4;
        if (mk0.x > 0) p0 = __ldg(&y4[(r + 0) * C4 + t]);
        if (mk0.y > 0) p1 = __ldg(&y4[(r + 1) * C4 + t]);
        if (mk0.z > 0) p2 = __ldg(&y4[(r + 2) * C4 + t]);
        if (mk0.w > 0) p3 = __ldg(&y4[(r + 3) * C4 + t]);
    }

    if (bid < 32) {
        // ===== stats: fold 296 partial slots for channels [32*bid, 32*bid+32) =====
        const int c = bid * 32 + lane;
        float s = 0.0f, q = 0.0f;
        for (int p = w; p < NBLK; p += 32) {
            s += g_psum[p][c];
            q += g_psq [p][c];
        }
        sfs[w][lane] = s;
        sfq[w][lane] = q;

        if (w == 0) {
            int n = 0;
            for (int p = lane; p < NBLK; p += 32) n += g_pcnt[p];
            #pragma unroll
            for (int o = 16; o; o >>= 1) n += __shfl_down_sync(0xffffffffu, n, o);
            if (lane == 0) sn = n;
        }
        __syncthreads();

        if (w == 0) {
            float S = 0.0f, Q = 0.0f;
            #pragma unroll
            for (int i = 0; i < 32; i++) { S += sfs[i][lane]; Q += sfq[i][lane]; }
            const float nf   = (float)sn;
            const float mean = S / nf;
            const float var  = (Q - S * S / nf) / (nf - 1.0f);
            const float sd   = sqrtf(var);
            const float sc   = __ldg(&gamma[c]) / (sd + EPSF);
            g_scale[c] = sc;
            g_shift[c] = __ldg(&beta[c]) - mean * sc;
            __threadfence();
        }
        __syncthreads();
        if (tid == 0) atomicAdd(&g_sdone, 1);
    }

    // ===== wait for all 32 stats blocks =====
    if (tid == 0) {
        while (*(volatile int*)&g_sdone != 32) { }
        __threadfence();
    }
    __syncthreads();

    const float4 sc = reinterpret_cast<const float4*>(g_scale)[t];
    const float4 sh = reinterpret_cast<const float4*>(g_shift)[t];

    if (bid >= 32) {
        // consume prefetched quad
        if (r4_0 < R4TOT) {
            const int r = r4_0 * 4;
            if (mk0.x > 0) {
                p0.x = fmaf(p0.x, sc.x, sh.x); p0.y = fmaf(p0.y, sc.y, sh.y);
                p0.z = fmaf(p0.z, sc.z, sh.z); p0.w = fmaf(p0.w, sc.w, sh.w);
                __stcs(&out4[(r + 0) * C4 + t], p0);
            }
            if (mk0.y > 0) {
                p1.x = fmaf(p1.x, sc.x, sh.x); p1.y = fmaf(p1.y, sc.y, sh.y);
                p1.z = fmaf(p1.z, sc.z, sh.z); p1.w = fmaf(p1.w, sc.w, sh.w);
                __stcs(&out4[(r + 1) * C4 + t], p1);
            }
            if (mk0.z > 0) {
                p2.x = fmaf(p2.x, sc.x, sh.x); p2.y = fmaf(p2.y, sc.y, sh.y);
                p2.z = fmaf(p2.z, sc.z, sh.z); p2.w = fmaf(p2.w, sc.w, sh.w);
                __stcs(&out4[(r + 2) * C4 + t], p2);
            }
            if (mk0.w > 0) {
                p3.x = fmaf(p3.x, sc.x, sh.x); p3.y = fmaf(p3.y, sc.y, sh.y);
                p3.z = fmaf(p3.z, sc.z, sh.z); p3.w = fmaf(p3.w, sc.w, sh.w);
                __stcs(&out4[(r + 3) * C4 + t], p3);
            }
        }
        // remaining iterations
        for (int r4 = r4_0 + NB3 * 4; r4 < R4TOT; r4 += NB3 * 4) {
            norm_quad(y4, __ldg(&mask4[r4]), out4, sc, sh, r4, t);
        }
    } else {
        // stats blocks also normalize their range (no prefetch)
        for (int r4 = bid * 4 + g; r4 < R4TOT; r4 += NB3 * 4) {
            norm_quad(y4, __ldg(&mask4[r4]), out4, sc, sh, r4, t);
        }
    }
}

extern "C" void kernel_launch(void* const* d_in, const int* in_sizes, int n_in,
                              void* d_out, int out_size) {
    const float* y     = (const float*)d_in[0];
    const int*   mask  = (const int*)  d_in[1];
    const float* gamma = (const float*)d_in[2];
    const float* beta  = (const float*)d_in[3];
    float*       out   = (float*)d_out;

    mn_main<<<NBLK, 1024>>>((const float4*)y, (const int4*)mask, (float4*)out);
    mn_finish<<<NB3, 1024>>>((const float4*)y, (const int4*)mask, gamma, beta,
                             (float4*)out);
}

// round 16
// speedup vs baseline: 1.0955x; 1.0955x over previous
#include <cuda_runtime.h>
#include <math.h>

// MaskedNorm: B=8, T=4096, C=1024 fp32. Three kernels chained with
// Programmatic Dependent Launch (PDL) to overlap launch ramps/tails:
// k1: dense read; masked rows -> partial sums, unmasked rows -> copy to out
// k2: fold partials -> per-channel scale/shift  (waits on k1 via griddepcontrol)
// k3: normalize masked rows (prefetches mask+y BEFORE waiting on k2)

#define CCH   1024
#define C4    (CCH / 4)      // 256 float4 per row
#define RTOT  32768          // B*T
#define R4TOT (RTOT / 4)     // 8192 row-quads
#define R2TOT (RTOT / 2)     // 16384 row-pairs
#define NBLK  296            // k1 blocks: 2/SM x 148 SMs (1024 thr each)
#define G3    2048           // k3 blocks: 16384/2048 = 8 iters exact
#define EPSF  1e-4f

__device__ __align__(16) float g_psum[NBLK][CCH];
__device__ __align__(16) float g_psq [NBLK][CCH];
__device__ int   g_pcnt[NBLK];
__device__ __align__(16) float g_scale[CCH];
__device__ __align__(16) float g_shift[CCH];

__device__ __forceinline__ void gdc_launch_dependents() {
    asm volatile("griddepcontrol.launch_dependents;" ::: "memory");
}
__device__ __forceinline__ void gdc_wait() {
    asm volatile("griddepcontrol.wait;" ::: "memory");
}

__device__ __forceinline__ void acc4(float4& s, float4& q, const float4 v) {
    s.x += v.x; s.y += v.y; s.z += v.z; s.w += v.w;
    q.x = fmaf(v.x, v.x, q.x);
    q.y = fmaf(v.y, v.y, q.y);
    q.z = fmaf(v.z, v.z, q.z);
    q.w = fmaf(v.w, v.w, q.w);
}

// ---------- k1: masked reduce + unmasked copy (dense streaming) ----------
__global__ __launch_bounds__(1024, 2)
void mn_main(const float4* __restrict__ y4, const int4* __restrict__ mask4,
             float4* __restrict__ out4) {
    __shared__ float4 ssum[4][256];
    __shared__ float4 ssq [4][256];
    __shared__ int    scnt[4];
    const int t = threadIdx.x & 255;   // channel slot (4 channels)
    const int g = threadIdx.x >> 8;    // row group 0..3
    const int p = blockIdx.x;

    float4 s = make_float4(0.f, 0.f, 0.f, 0.f);
    float4 q = make_float4(0.f, 0.f, 0.f, 0.f);
    int cnt = 0;

    for (int r4 = p * 4 + g; r4 < R4TOT; r4 += NBLK * 4) {
        const int  r  = r4 * 4;
        const int4 mk = __ldg(&mask4[r4]);
        if (mk.x > 0) { acc4(s, q, __ldg(&y4[(r + 0) * C4 + t])); cnt++; }
        else          { __stcs(&out4[(r + 0) * C4 + t], __ldcs(&y4[(r + 0) * C4 + t])); }
        if (mk.y > 0) { acc4(s, q, __ldg(&y4[(r + 1) * C4 + t])); cnt++; }
        else          { __stcs(&out4[(r + 1) * C4 + t], __ldcs(&y4[(r + 1) * C4 + t])); }
        if (mk.z > 0) { acc4(s, q, __ldg(&y4[(r + 2) * C4 + t])); cnt++; }
        else          { __stcs(&out4[(r + 2) * C4 + t], __ldcs(&y4[(r + 2) * C4 + t])); }
        if (mk.w > 0) { acc4(s, q, __ldg(&y4[(r + 3) * C4 + t])); cnt++; }
        else          { __stcs(&out4[(r + 3) * C4 + t], __ldcs(&y4[(r + 3) * C4 + t])); }
    }
    ssum[g][t] = s;
    ssq [g][t] = q;
    if (t == 0) scnt[g] = cnt;   // identical across t within a group
    __syncthreads();

    if (g == 0) {
        float4 S = ssum[0][t], Q = ssq[0][t];
        #pragma unroll
        for (int i = 1; i < 4; i++) {
            const float4 a = ssum[i][t], b = ssq[i][t];
            S.x += a.x; S.y += a.y; S.z += a.z; S.w += a.w;
            Q.x += b.x; Q.y += b.y; Q.z += b.z; Q.w += b.w;
        }
        reinterpret_cast<float4*>(g_psum[p])[t] = S;
        reinterpret_cast<float4*>(g_psq [p])[t] = Q;
        if (t == 0) g_pcnt[p] = scnt[0] + scnt[1] + scnt[2] + scnt[3];
    }
    gdc_launch_dependents();   // partials for this block are written
}

// ---------- k2: fold partials -> scale/shift (32 blocks x 1024 thr, PDL) ----------
__global__ __launch_bounds__(1024, 2)
void mn_stats(const float* __restrict__ gamma, const float* __restrict__ beta) {
    __shared__ float sfs[32][33];
    __shared__ float sfq[32][33];
    __shared__ int   sn;
    const int lane = threadIdx.x & 31;
    const int w    = threadIdx.x >> 5;
    const int c    = blockIdx.x * 32 + lane;

    // gamma/beta are kernel inputs (not produced by k1) -> load before wait.
    const float gm = __ldg(&gamma[c]);
    const float bt = __ldg(&beta[c]);

    gdc_wait();   // k1's partials now visible

    float s = 0.0f, q = 0.0f;
    for (int p = w; p < NBLK; p += 32) {
        s += g_psum[p][c];
        q += g_psq [p][c];
    }
    sfs[w][lane] = s;
    sfq[w][lane] = q;

    if (w == 0) {
        int n = 0;
        for (int p = lane; p < NBLK; p += 32) n += g_pcnt[p];
        #pragma unroll
        for (int o = 16; o; o >>= 1) n += __shfl_down_sync(0xffffffffu, n, o);
        if (lane == 0) sn = n;
    }
    __syncthreads();

    if (w == 0) {
        float S = 0.0f, Q = 0.0f;
        #pragma unroll
        for (int i = 0; i < 32; i++) { S += sfs[i][lane]; Q += sfq[i][lane]; }
        const float nf   = (float)sn;
        const float mean = S / nf;
        const float var  = (Q - S * S / nf) / (nf - 1.0f);
        const float sd   = sqrtf(var);
        const float sc   = gm / (sd + EPSF);
        g_scale[c] = sc;
        g_shift[c] = bt - mean * sc;   // out = fma(y, sc, shift)
    }
    __syncthreads();
    gdc_launch_dependents();   // scale/shift written
}

// ---------- k3: normalize masked rows (prefetch before PDL wait) ----------
__global__ __launch_bounds__(256, 8)
void mn_norm(const float4* __restrict__ y4, const int* __restrict__ mask,
             float4* __restrict__ out4) {
    const int t = threadIdx.x;

    // Prefetch first row-pair: mask + y do NOT depend on k2 -> overlap its run.
    const int r0 = blockIdx.x * 2;
    const int m0 = __ldg(&mask[r0 + 0]);
    const int m1 = __ldg(&mask[r0 + 1]);
    float4 v0, v1;
    if (m0 > 0) v0 = __ldg(&y4[(r0 + 0) * C4 + t]);
    if (m1 > 0) v1 = __ldg(&y4[(r0 + 1) * C4 + t]);

    gdc_wait();   // scale/shift now visible

    const float4 sc = reinterpret_cast<const float4*>(g_scale)[t];
    const float4 sh = reinterpret_cast<const float4*>(g_shift)[t];

    if (m0 > 0) {
        v0.x = fmaf(v0.x, sc.x, sh.x); v0.y = fmaf(v0.y, sc.y, sh.y);
        v0.z = fmaf(v0.z, sc.z, sh.z); v0.w = fmaf(v0.w, sc.w, sh.w);
        __stcs(&out4[(r0 + 0) * C4 + t], v0);
    }
    if (m1 > 0) {
        v1.x = fmaf(v1.x, sc.x, sh.x); v1.y = fmaf(v1.y, sc.y, sh.y);
        v1.z = fmaf(v1.z, sc.z, sh.z); v1.w = fmaf(v1.w, sc.w, sh.w);
        __stcs(&out4[(r0 + 1) * C4 + t], v1);
    }

    #pragma unroll 1
    for (int r2 = blockIdx.x + G3; r2 < R2TOT; r2 += G3) {
        const int r  = r2 * 2;
        const int ma = __ldg(&mask[r + 0]);
        const int mb = __ldg(&mask[r + 1]);
        if (ma > 0) {
            float4 v = __ldg(&y4[(r + 0) * C4 + t]);
            v.x = fmaf(v.x, sc.x, sh.x); v.y = fmaf(v.y, sc.y, sh.y);
            v.z = fmaf(v.z, sc.z, sh.z); v.w = fmaf(v.w, sc.w, sh.w);
            __stcs(&out4[(r + 0) * C4 + t], v);
        }
        if (mb > 0) {
            float4 v = __ldg(&y4[(r + 1) * C4 + t]);
            v.x = fmaf(v.x, sc.x, sh.x); v.y = fmaf(v.y, sc.y, sh.y);
            v.z = fmaf(v.z, sc.z, sh.z); v.w = fmaf(v.w, sc.w, sh.w);
            __stcs(&out4[(r + 1) * C4 + t], v);
        }
    }
}

extern "C" void kernel_launch(void* const* d_in, const int* in_sizes, int n_in,
                              void* d_out, int out_size) {
    const float* y     = (const float*)d_in[0];
    const int*   mask  = (const int*)  d_in[1];
    const float* gamma = (const float*)d_in[2];
    const float* beta  = (const float*)d_in[3];
    float*       out   = (float*)d_out;

    // k1: normal launch
    mn_main<<<NBLK, 1024>>>((const float4*)y, (const int4*)mask, (float4*)out);

    // k2, k3: programmatic dependent launches (overlap with producer tail)
    cudaLaunchAttribute attr;
    attr.id = cudaLaunchAttributeProgrammaticStreamSerialization;
    attr.val.programmaticStreamSerializationAllowed = 1;

    {
        cudaLaunchConfig_t cfg = {};
        cfg.gridDim  = dim3(32, 1, 1);
        cfg.blockDim = dim3(1024, 1, 1);
        cfg.attrs    = &attr;
        cfg.numAttrs = 1;
        cfg.stream   = 0;
        cudaLaunchKernelEx(&cfg, mn_stats, gamma, beta);
    }
    {
        cudaLaunchConfig_t cfg = {};
        cfg.gridDim  = dim3(G3, 1, 1);
        cfg.blockDim = dim3(256, 1, 1);
        cfg.attrs    = &attr;
        cfg.numAttrs = 1;
        cfg.stream   = 0;
        cudaLaunchKernelEx(&cfg, mn_norm, (const float4*)y, mask, (float4*)out);
    }
}